// round 8
// baseline (speedup 1.0000x reference)
#include <cuda_runtime.h>
#include <cstddef>
#include <cstdint>

#define N_NODES   100000
#define N_EDGES   50000
#define N_INC     3200000
#define D_IN      128
#define D_HID     32
#define N_CLASSES 40

// ---------------------------------------------------------------------------
// Scratch (static device globals)
// ---------------------------------------------------------------------------
__device__ float g_xw[(size_t)N_NODES * D_HID];  // X@W1
__device__ float g_ef[(size_t)N_EDGES * D_HID];  // hyperedge features
__device__ float g_h1[(size_t)N_NODES * D_HID];  // hidden layer
__device__ float g_dinv[N_NODES];
__device__ float g_binv[N_EDGES];

__device__ int g_cnt_n[N_NODES];
__device__ int g_cnt_e[N_EDGES];
__device__ int g_off_n[N_NODES + 1];
__device__ int g_off_e[N_EDGES + 1];
__device__ int g_adj_n[N_INC];    // edge ids grouped by node
__device__ int g_adj_e[N_INC];    // node ids grouped by edge
__device__ int g_rank_n[N_INC];   // rank of pair i within its node bucket
__device__ int g_rank_e[N_INC];   // rank of pair i within its edge bucket
__device__ int g_aux_n[128];
__device__ int g_aux_e[128];

#define NB_N ((N_NODES + 1023) / 1024)   // 98
#define NB_E ((N_EDGES + 1023) / 1024)   // 49

// ---------------------------------------------------------------------------
// cp.async helpers
// ---------------------------------------------------------------------------
__device__ __forceinline__ void cp_async16(void* dst_smem, const void* src, int src_bytes) {
    uint32_t d = (uint32_t)__cvta_generic_to_shared(dst_smem);
    asm volatile("cp.async.cg.shared.global [%0], [%1], 16, %2;"
                 :: "r"(d), "l"(src), "r"(src_bytes));
}
__device__ __forceinline__ void cp_commit() {
    asm volatile("cp.async.commit_group;");
}
template <int NG>
__device__ __forceinline__ void cp_wait() {
    asm volatile("cp.async.wait_group %0;" :: "n"(NG));
}

// ---------------------------------------------------------------------------
// Degree counting + per-pair rank capture (the atomic doubles as rank source)
// ---------------------------------------------------------------------------
__global__ void degree_rank_kernel(const int* __restrict__ nidx,
                                   const int* __restrict__ eidx,
                                   int* __restrict__ cn, int* __restrict__ ce,
                                   int* __restrict__ rank_n, int* __restrict__ rank_e,
                                   int n) {
    int i = blockIdx.x * blockDim.x + threadIdx.x;
    if (i < n) {
        rank_n[i] = atomicAdd(cn + nidx[i], 1);
        rank_e[i] = atomicAdd(ce + eidx[i], 1);
    }
}

// ---------------------------------------------------------------------------
// Combined block scan (node + edge arrays in one grid) + fused 1/deg
// ---------------------------------------------------------------------------
__global__ void scan_block2(const int* __restrict__ cnt_n, int* __restrict__ off_n,
                            int* __restrict__ aux_n, float* __restrict__ dinv,
                            const int* __restrict__ cnt_e, int* __restrict__ off_e,
                            int* __restrict__ aux_e, float* __restrict__ binv) {
    __shared__ int sm[1024];
    const int b = blockIdx.x;
    const int* in;  int* out; int* aux; float* inv; int n; int bb;
    if (b < NB_N) { in = cnt_n; out = off_n; aux = aux_n; inv = dinv; n = N_NODES; bb = b; }
    else          { in = cnt_e; out = off_e; aux = aux_e; inv = binv; n = N_EDGES; bb = b - NB_N; }

    const int tid = threadIdx.x;
    const int i = bb * 1024 + tid;
    int v = (i < n) ? in[i] : 0;
    if (i < n) inv[i] = (v > 0) ? (1.0f / (float)v) : 0.0f;
    sm[tid] = v;
    __syncthreads();
#pragma unroll
    for (int o = 1; o < 1024; o <<= 1) {
        int t = (tid >= o) ? sm[tid - o] : 0;
        __syncthreads();
        sm[tid] += t;
        __syncthreads();
    }
    if (i < n) out[i] = sm[tid] - v;            // exclusive
    if (tid == 1023) aux[bb] = sm[1023];
}

// Parallel aux scan (both arrays) — 1 block, 128 threads.
__global__ void scan_aux2(int* __restrict__ aux_n, int* __restrict__ aux_e) {
    __shared__ int sm[128];
    const int t = threadIdx.x;

    int orig = (t < NB_N) ? aux_n[t] : 0;
    sm[t] = orig;
    __syncthreads();
#pragma unroll
    for (int o = 1; o < 128; o <<= 1) {
        int v = (t >= o) ? sm[t - o] : 0;
        __syncthreads();
        sm[t] += v;
        __syncthreads();
    }
    if (t < NB_N) aux_n[t] = sm[t] - orig;
    __syncthreads();

    orig = (t < NB_E) ? aux_e[t] : 0;
    sm[t] = orig;
    __syncthreads();
#pragma unroll
    for (int o = 1; o < 128; o <<= 1) {
        int v = (t >= o) ? sm[t - o] : 0;
        __syncthreads();
        sm[t] += v;
        __syncthreads();
    }
    if (t < NB_E) aux_e[t] = sm[t] - orig;
}

// Combined add-pass; writes the sentinels.
__global__ void scan_add2(int* __restrict__ off_n, const int* __restrict__ aux_n,
                          int* __restrict__ off_e, const int* __restrict__ aux_e) {
    const int b = blockIdx.x;
    if (b < NB_N) {
        int i = b * 1024 + threadIdx.x;
        if (i < N_NODES) off_n[i] += aux_n[b];
        if (i == 0) off_n[N_NODES] = N_INC;
    } else {
        int i = (b - NB_N) * 1024 + threadIdx.x;
        if (i < N_EDGES) off_e[i] += aux_e[b - NB_N];
        if (i == 0) off_e[N_EDGES] = N_INC;
    }
}

// ---------------------------------------------------------------------------
// CSR fill — atomic-free: position = off[key] + precomputed rank.
// ---------------------------------------------------------------------------
__global__ void fill_csr(const int* __restrict__ nidx, const int* __restrict__ eidx,
                         const int* __restrict__ off_n, const int* __restrict__ off_e,
                         const int* __restrict__ rank_n, const int* __restrict__ rank_e,
                         int* __restrict__ adj_n, int* __restrict__ adj_e, int n) {
    int i = blockIdx.x * blockDim.x + threadIdx.x;
    if (i < n) {
        int v = nidx[i], e = eidx[i];
        adj_n[__ldg(off_n + v) + rank_n[i]] = e;
        adj_e[__ldg(off_e + e) + rank_e[i]] = v;
    }
}

// ---------------------------------------------------------------------------
// GEMM1: persistent, cp.async double-buffered.
// Y[N,32] = X[N,128] @ W[128,32]. 8 rows x 4 cols per thread.
// blockDim (8,8)=64 threads; tile = 64 rows; smem = W(16K) + 2 X-buffers(33K ea).
// ---------------------------------------------------------------------------
#define G_TR   64                       // tile rows
#define G_XST  (D_IN + 4)               // padded X row stride in smem
#define G_SMEM ((D_IN * D_HID + 2 * G_TR * G_XST) * (int)sizeof(float))  // 83968 B
#define G_GRID 296                      // 2 blocks/SM * 148 SMs
#define G_NT   ((N_NODES + G_TR - 1) / G_TR)   // 1563 tiles

__global__ void gemm1_kernel(const float* __restrict__ X,
                             const float* __restrict__ W,
                             float* __restrict__ Y, int N) {
    constexpr int K = D_IN, F = D_HID;
    extern __shared__ float smem[];
    float* ws  = smem;                       // K*F
    float* xs0 = smem + K * F;               // G_TR * G_XST
    float* xs1 = xs0 + G_TR * G_XST;
    const int tx = threadIdx.x;              // 0..7 (col quad)
    const int ty = threadIdx.y;              // 0..7 (row slot)
    const int tid = ty * 8 + tx;

    for (int i = tid; i < K * F / 4; i += 64)
        ((float4*)ws)[i] = ((const float4*)W)[i];

    int t = blockIdx.x;
    // prefetch first tile into buffer 0
    if (t < G_NT) {
        const int row0 = t * G_TR;
        for (int i = tid; i < G_TR * (K / 4); i += 64) {
            int r = i >> 5, c = i & 31;
            int sz = (row0 + r < N) ? 16 : 0;
            cp_async16(xs0 + r * G_XST + c * 4,
                       X + (size_t)(row0 + r) * K + c * 4, sz);
        }
        cp_commit();
    }

    float* bufs[2] = { xs0, xs1 };
    int pb = 0;
    for (; t < G_NT; t += G_GRID) {
        const int tn = t + G_GRID;
        if (tn < G_NT) {
            const int row0n = tn * G_TR;
            float* nb = bufs[pb ^ 1];
            for (int i = tid; i < G_TR * (K / 4); i += 64) {
                int r = i >> 5, c = i & 31;
                int sz = (row0n + r < N) ? 16 : 0;
                cp_async16(nb + r * G_XST + c * 4,
                           X + (size_t)(row0n + r) * K + c * 4, sz);
            }
            cp_commit();
            cp_wait<1>();      // current buffer's group done; next still in flight
        } else {
            cp_wait<0>();
        }
        __syncthreads();

        const float* xs = bufs[pb];
        const int row0 = t * G_TR;

        float4 acc[8];
#pragma unroll
        for (int r = 0; r < 8; r++) acc[r] = make_float4(0.f, 0.f, 0.f, 0.f);

#pragma unroll
        for (int k = 0; k < K; k += 4) {
            float4 w0 = *(const float4*)&ws[(k + 0) * F + tx * 4];
            float4 w1 = *(const float4*)&ws[(k + 1) * F + tx * 4];
            float4 w2 = *(const float4*)&ws[(k + 2) * F + tx * 4];
            float4 w3 = *(const float4*)&ws[(k + 3) * F + tx * 4];
#pragma unroll
            for (int r = 0; r < 8; r++) {
                float4 xv = *(const float4*)&xs[(ty + 8 * r) * G_XST + k];
                acc[r].x += xv.x * w0.x + xv.y * w1.x + xv.z * w2.x + xv.w * w3.x;
                acc[r].y += xv.x * w0.y + xv.y * w1.y + xv.z * w2.y + xv.w * w3.y;
                acc[r].z += xv.x * w0.z + xv.y * w1.z + xv.z * w2.z + xv.w * w3.z;
                acc[r].w += xv.x * w0.w + xv.y * w1.w + xv.z * w2.w + xv.w * w3.w;
            }
        }
#pragma unroll
        for (int r = 0; r < 8; r++) {
            const int row = row0 + ty + 8 * r;
            if (row < N) *(float4*)&Y[(size_t)row * F + tx * 4] = acc[r];
        }
        __syncthreads();   // all reads of bufs[pb] done before it is refilled next iter
        pb ^= 1;
    }
}

// ---------------------------------------------------------------------------
// float4 CSR gather: warp per dst row; lane = (sub-row r = lane/8, quad q = lane%8).
// MODE 0: dst = scale*sum   MODE 1: dst = relu(scale*sum + bias)
// ---------------------------------------------------------------------------
template <int MODE>
__global__ void gather_kernel(const int* __restrict__ off,
                              const int* __restrict__ adj,
                              const float* __restrict__ src,
                              const float* __restrict__ scale,
                              const float* __restrict__ bias,
                              float* __restrict__ dst, int nrows) {
    const int row  = (blockIdx.x * blockDim.x + threadIdx.x) >> 5;
    const int lane = threadIdx.x & 31;
    if (row >= nrows) return;
    const int r = lane >> 3;          // 0..3 sub-row slot
    const int q = lane & 7;           // 0..7 quad

    const int s = off[row], e = off[row + 1];
    float4 a = make_float4(0.f, 0.f, 0.f, 0.f);
    int j = s;
    for (; j + 8 <= e; j += 8) {
        int m0 = adj[j + r];
        int m1 = adj[j + 4 + r];
        float4 v0 = *(const float4*)(src + (size_t)m0 * D_HID + q * 4);
        float4 v1 = *(const float4*)(src + (size_t)m1 * D_HID + q * 4);
        a.x += v0.x + v1.x; a.y += v0.y + v1.y;
        a.z += v0.z + v1.z; a.w += v0.w + v1.w;
    }
    for (; j < e; j += 4) {
        if (j + r < e) {
            int m = adj[j + r];
            float4 v = *(const float4*)(src + (size_t)m * D_HID + q * 4);
            a.x += v.x; a.y += v.y; a.z += v.z; a.w += v.w;
        }
    }
#pragma unroll
    for (int o = 8; o <= 16; o <<= 1) {
        a.x += __shfl_xor_sync(0xffffffffu, a.x, o);
        a.y += __shfl_xor_sync(0xffffffffu, a.y, o);
        a.z += __shfl_xor_sync(0xffffffffu, a.z, o);
        a.w += __shfl_xor_sync(0xffffffffu, a.w, o);
    }

    if (r == 0) {
        const float f = scale[row];
        if (MODE == 0) {
            a.x *= f; a.y *= f; a.z *= f; a.w *= f;
        } else {
            float4 bb = *(const float4*)(bias + q * 4);
            a.x = fmaxf(a.x * f + bb.x, 0.f);
            a.y = fmaxf(a.y * f + bb.y, 0.f);
            a.z = fmaxf(a.z * f + bb.z, 0.f);
            a.w = fmaxf(a.w * f + bb.w, 0.f);
        }
        *(float4*)(dst + (size_t)row * D_HID + q * 4) = a;
    }
}

// ---------------------------------------------------------------------------
// Fused final: float4 node-gather + @W2 [32,40] + b2 + log_softmax.
// ---------------------------------------------------------------------------
__global__ void gather_w2_logsoftmax(const int* __restrict__ off,
                                     const int* __restrict__ adj,
                                     const float* __restrict__ src,
                                     const float* __restrict__ dinv,
                                     const float* __restrict__ W2,
                                     const float* __restrict__ b2,
                                     float* __restrict__ out, int nrows) {
    __shared__ float w2s[D_HID * N_CLASSES];
    __shared__ float b2s[N_CLASSES];
    {
        const int t = threadIdx.x;
        for (int i = t; i < D_HID * N_CLASSES; i += blockDim.x) w2s[i] = W2[i];
        if (t < N_CLASSES) b2s[t] = b2[t];
    }
    __syncthreads();

    const int row  = (blockIdx.x * blockDim.x + threadIdx.x) >> 5;
    const int lane = threadIdx.x & 31;
    if (row >= nrows) return;
    const int r = lane >> 3;
    const int q = lane & 7;

    const int s = off[row], e = off[row + 1];
    float4 a = make_float4(0.f, 0.f, 0.f, 0.f);
    int j = s;
    for (; j + 8 <= e; j += 8) {
        int m0 = adj[j + r];
        int m1 = adj[j + 4 + r];
        float4 v0 = *(const float4*)(src + (size_t)m0 * D_HID + q * 4);
        float4 v1 = *(const float4*)(src + (size_t)m1 * D_HID + q * 4);
        a.x += v0.x + v1.x; a.y += v0.y + v1.y;
        a.z += v0.z + v1.z; a.w += v0.w + v1.w;
    }
    for (; j < e; j += 4) {
        if (j + r < e) {
            int m = adj[j + r];
            float4 v = *(const float4*)(src + (size_t)m * D_HID + q * 4);
            a.x += v.x; a.y += v.y; a.z += v.z; a.w += v.w;
        }
    }
#pragma unroll
    for (int o = 8; o <= 16; o <<= 1) {
        a.x += __shfl_xor_sync(0xffffffffu, a.x, o);
        a.y += __shfl_xor_sync(0xffffffffu, a.y, o);
        a.z += __shfl_xor_sync(0xffffffffu, a.z, o);
        a.w += __shfl_xor_sync(0xffffffffu, a.w, o);
    }

    const float di = dinv[row];
    a.x *= di; a.y *= di; a.z *= di; a.w *= di;
    // feature k lives on lane q = k>>2 (all r replicas agree), component k&3.

    float z0 = 0.f, z1 = 0.f;
#pragma unroll
    for (int k = 0; k < D_HID; k++) {
        float comp = ((k & 3) == 0) ? a.x : ((k & 3) == 1) ? a.y
                    : ((k & 3) == 2) ? a.z : a.w;
        float ak = __shfl_sync(0xffffffffu, comp, k >> 2);
        z0 += ak * w2s[k * N_CLASSES + lane];
        if (lane < N_CLASSES - 32) z1 += ak * w2s[k * N_CLASSES + 32 + lane];
    }
    z0 += b2s[lane];
    z1 = (lane < N_CLASSES - 32) ? (z1 + b2s[32 + lane]) : -1e30f;

    float m = fmaxf(z0, z1);
#pragma unroll
    for (int o = 16; o; o >>= 1) m = fmaxf(m, __shfl_xor_sync(0xffffffffu, m, o));
    float ex = __expf(z0 - m) + ((lane < N_CLASSES - 32) ? __expf(z1 - m) : 0.f);
#pragma unroll
    for (int o = 16; o; o >>= 1) ex += __shfl_xor_sync(0xffffffffu, ex, o);
    const float lse = __logf(ex) + m;

    out[(size_t)row * N_CLASSES + lane] = z0 - lse;
    if (lane < N_CLASSES - 32)
        out[(size_t)row * N_CLASSES + 32 + lane] = z1 - lse;
}

// ---------------------------------------------------------------------------
// Launch
// ---------------------------------------------------------------------------
extern "C" void kernel_launch(void* const* d_in, const int* in_sizes, int n_in,
                              void* d_out, int out_size) {
    const float* x    = (const float*)d_in[0];
    const int*   nidx = (const int*)d_in[1];
    const int*   eidx = (const int*)d_in[2];
    const float* W1   = (const float*)d_in[3];
    const float* b1   = (const float*)d_in[4];
    const float* W2   = (const float*)d_in[5];
    const float* b2   = (const float*)d_in[6];
    float* out = (float*)d_out;

    float *xw, *ef, *h1, *dinv, *binv;
    int *cnt_n, *cnt_e, *off_n, *off_e, *adj_n, *adj_e, *rank_n, *rank_e, *aux_n, *aux_e;
    cudaGetSymbolAddress((void**)&xw,     g_xw);
    cudaGetSymbolAddress((void**)&ef,     g_ef);
    cudaGetSymbolAddress((void**)&h1,     g_h1);
    cudaGetSymbolAddress((void**)&dinv,   g_dinv);
    cudaGetSymbolAddress((void**)&binv,   g_binv);
    cudaGetSymbolAddress((void**)&cnt_n,  g_cnt_n);
    cudaGetSymbolAddress((void**)&cnt_e,  g_cnt_e);
    cudaGetSymbolAddress((void**)&off_n,  g_off_n);
    cudaGetSymbolAddress((void**)&off_e,  g_off_e);
    cudaGetSymbolAddress((void**)&adj_n,  g_adj_n);
    cudaGetSymbolAddress((void**)&adj_e,  g_adj_e);
    cudaGetSymbolAddress((void**)&rank_n, g_rank_n);
    cudaGetSymbolAddress((void**)&rank_e, g_rank_e);
    cudaGetSymbolAddress((void**)&aux_n,  g_aux_n);
    cudaGetSymbolAddress((void**)&aux_e,  g_aux_e);

    cudaFuncSetAttribute(gemm1_kernel,
                         cudaFuncAttributeMaxDynamicSharedMemorySize, G_SMEM);

    // ---- degrees + per-pair ranks ----
    cudaMemsetAsync(cnt_n, 0, N_NODES * sizeof(int));
    cudaMemsetAsync(cnt_e, 0, N_EDGES * sizeof(int));
    degree_rank_kernel<<<(N_INC + 255) / 256, 256>>>(nidx, eidx, cnt_n, cnt_e,
                                                     rank_n, rank_e, N_INC);

    // ---- CSR build: combined scans (invert fused into scan_block2) ----
    scan_block2<<<NB_N + NB_E, 1024>>>(cnt_n, off_n, aux_n, dinv,
                                       cnt_e, off_e, aux_e, binv);
    scan_aux2<<<1, 128>>>(aux_n, aux_e);
    gemm1_kernel<<<G_GRID, dim3(8, 8), G_SMEM>>>(x, W1, xw, N_NODES);  // independent; placed for ncu -s 5
    scan_add2<<<NB_N + NB_E, 1024>>>(off_n, aux_n, off_e, aux_e);
    fill_csr<<<(N_INC + 255) / 256, 256>>>(nidx, eidx, off_n, off_e,
                                           rank_n, rank_e, adj_n, adj_e, N_INC);

    // ---- layer 1: h1 = relu(Dinv H Binv H^T (x W1) + b1) ----
    gather_kernel<0><<<(N_EDGES + 7) / 8, 256>>>(off_e, adj_e, xw, binv, nullptr, ef, N_EDGES);
    gather_kernel<1><<<(N_NODES + 7) / 8, 256>>>(off_n, adj_n, ef, dinv, b1, h1, N_NODES);

    // ---- layer 2 (aggregate in hidden space; W2 applied post-aggregation) ----
    gather_kernel<0><<<(N_EDGES + 7) / 8, 256>>>(off_e, adj_e, h1, binv, nullptr, ef, N_EDGES);
    gather_w2_logsoftmax<<<(N_NODES + 7) / 8, 256>>>(off_n, adj_n, ef, dinv, W2, b2, out, N_NODES);
}

// round 9
// speedup vs baseline: 1.4920x; 1.4920x over previous
#include <cuda_runtime.h>
#include <cstddef>
#include <cstdint>

#define N_NODES   100000
#define N_EDGES   50000
#define N_INC     3200000
#define D_IN      128
#define D_HID     32
#define N_CLASSES 40

// ---------------------------------------------------------------------------
// Scratch (static device globals)
// ---------------------------------------------------------------------------
__device__ float g_xw[(size_t)N_NODES * D_HID];  // X@W1
__device__ float g_ef[(size_t)N_EDGES * D_HID];  // hyperedge features
__device__ float g_h1[(size_t)N_NODES * D_HID];  // hidden layer
__device__ float g_dinv[N_NODES];
__device__ float g_binv[N_EDGES];

__device__ int g_cnt_n[N_NODES];
__device__ int g_cnt_e[N_EDGES];
__device__ int g_off_n[N_NODES + 1];
__device__ int g_off_e[N_EDGES + 1];
__device__ int g_adj_n[N_INC];    // edge ids grouped by node
__device__ int g_adj_e[N_INC];    // node ids grouped by edge
__device__ int g_rank_n[N_INC];   // rank of pair i within its node bucket
__device__ int g_rank_e[N_INC];   // rank of pair i within its edge bucket
__device__ int g_aux_n[128];
__device__ int g_aux_e[128];

#define NB_N ((N_NODES + 1023) / 1024)   // 98
#define NB_E ((N_EDGES + 1023) / 1024)   // 49

// ---------------------------------------------------------------------------
// Degree counting + per-pair rank capture (the atomic doubles as rank source)
// ---------------------------------------------------------------------------
__global__ void degree_rank_kernel(const int* __restrict__ nidx,
                                   const int* __restrict__ eidx,
                                   int* __restrict__ cn, int* __restrict__ ce,
                                   int* __restrict__ rank_n, int* __restrict__ rank_e,
                                   int n) {
    int i = blockIdx.x * blockDim.x + threadIdx.x;
    if (i < n) {
        rank_n[i] = atomicAdd(cn + nidx[i], 1);
        rank_e[i] = atomicAdd(ce + eidx[i], 1);
    }
}

// ---------------------------------------------------------------------------
// Combined block scan (node + edge arrays in one grid) + fused 1/deg
// ---------------------------------------------------------------------------
__global__ void scan_block2(const int* __restrict__ cnt_n, int* __restrict__ off_n,
                            int* __restrict__ aux_n, float* __restrict__ dinv,
                            const int* __restrict__ cnt_e, int* __restrict__ off_e,
                            int* __restrict__ aux_e, float* __restrict__ binv) {
    __shared__ int sm[1024];
    const int b = blockIdx.x;
    const int* in;  int* out; int* aux; float* inv; int n; int bb;
    if (b < NB_N) { in = cnt_n; out = off_n; aux = aux_n; inv = dinv; n = N_NODES; bb = b; }
    else          { in = cnt_e; out = off_e; aux = aux_e; inv = binv; n = N_EDGES; bb = b - NB_N; }

    const int tid = threadIdx.x;
    const int i = bb * 1024 + tid;
    int v = (i < n) ? in[i] : 0;
    if (i < n) inv[i] = (v > 0) ? (1.0f / (float)v) : 0.0f;
    sm[tid] = v;
    __syncthreads();
#pragma unroll
    for (int o = 1; o < 1024; o <<= 1) {
        int t = (tid >= o) ? sm[tid - o] : 0;
        __syncthreads();
        sm[tid] += t;
        __syncthreads();
    }
    if (i < n) out[i] = sm[tid] - v;            // exclusive
    if (tid == 1023) aux[bb] = sm[1023];
}

// Parallel aux scan (both arrays) — 1 block, 128 threads.
__global__ void scan_aux2(int* __restrict__ aux_n, int* __restrict__ aux_e) {
    __shared__ int sm[128];
    const int t = threadIdx.x;

    int orig = (t < NB_N) ? aux_n[t] : 0;
    sm[t] = orig;
    __syncthreads();
#pragma unroll
    for (int o = 1; o < 128; o <<= 1) {
        int v = (t >= o) ? sm[t - o] : 0;
        __syncthreads();
        sm[t] += v;
        __syncthreads();
    }
    if (t < NB_N) aux_n[t] = sm[t] - orig;
    __syncthreads();

    orig = (t < NB_E) ? aux_e[t] : 0;
    sm[t] = orig;
    __syncthreads();
#pragma unroll
    for (int o = 1; o < 128; o <<= 1) {
        int v = (t >= o) ? sm[t - o] : 0;
        __syncthreads();
        sm[t] += v;
        __syncthreads();
    }
    if (t < NB_E) aux_e[t] = sm[t] - orig;
}

// Combined add-pass; writes the sentinels.
__global__ void scan_add2(int* __restrict__ off_n, const int* __restrict__ aux_n,
                          int* __restrict__ off_e, const int* __restrict__ aux_e) {
    const int b = blockIdx.x;
    if (b < NB_N) {
        int i = b * 1024 + threadIdx.x;
        if (i < N_NODES) off_n[i] += aux_n[b];
        if (i == 0) off_n[N_NODES] = N_INC;
    } else {
        int i = (b - NB_N) * 1024 + threadIdx.x;
        if (i < N_EDGES) off_e[i] += aux_e[b - NB_N];
        if (i == 0) off_e[N_EDGES] = N_INC;
    }
}

// ---------------------------------------------------------------------------
// CSR fill — atomic-free: position = off[key] + precomputed rank.
// ---------------------------------------------------------------------------
__global__ void fill_csr(const int* __restrict__ nidx, const int* __restrict__ eidx,
                         const int* __restrict__ off_n, const int* __restrict__ off_e,
                         const int* __restrict__ rank_n, const int* __restrict__ rank_e,
                         int* __restrict__ adj_n, int* __restrict__ adj_e, int n) {
    int i = blockIdx.x * blockDim.x + threadIdx.x;
    if (i < n) {
        int v = nidx[i], e = eidx[i];
        adj_n[__ldg(off_n + v) + rank_n[i]] = e;
        adj_e[__ldg(off_e + e) + rank_e[i]] = v;
    }
}

// ---------------------------------------------------------------------------
// GEMM1: Y[N,32] = X[N,128] @ W[128,32].
// blockDim (8,32)=256 threads; tile = 256 rows; 8 rows x 4 cols per thread.
// Dynamic smem = W(16 KB) + X tile(135 KB) = ~148 KB -> 1 block/SM, 16 warps.
// Thread rows: ty + 32*r (r=0..7); X LDS conflict-free with XST=132.
// ---------------------------------------------------------------------------
#define G_TR   256                      // tile rows
#define G_XST  (D_IN + 4)               // padded X row stride in smem
#define G_SMEM ((D_IN * D_HID + G_TR * G_XST) * (int)sizeof(float))  // 151552 B

__global__ void gemm1_kernel(const float* __restrict__ X,
                             const float* __restrict__ W,
                             float* __restrict__ Y, int N) {
    constexpr int K = D_IN, F = D_HID;
    extern __shared__ float smem[];
    float* ws = smem;                    // K*F
    float* xs = smem + K * F;            // G_TR * G_XST
    const int tx = threadIdx.x;          // 0..7  (col quad)
    const int ty = threadIdx.y;          // 0..31 (row slot)
    const int tid = ty * 8 + tx;

    for (int i = tid; i < K * F / 4; i += 256)
        ((float4*)ws)[i] = ((const float4*)W)[i];

    const int row0 = blockIdx.x * G_TR;
    for (int i = tid; i < G_TR * (K / 4); i += 256) {
        int r = i >> 5, c = i & 31;
        float4 v = make_float4(0.f, 0.f, 0.f, 0.f);
        if (row0 + r < N) v = ((const float4*)X)[(size_t)(row0 + r) * (K / 4) + c];
        *(float4*)&xs[r * G_XST + c * 4] = v;
    }
    __syncthreads();

    float4 acc[8];
#pragma unroll
    for (int r = 0; r < 8; r++) acc[r] = make_float4(0.f, 0.f, 0.f, 0.f);

#pragma unroll
    for (int k = 0; k < K; k += 4) {
        float4 w0 = *(const float4*)&ws[(k + 0) * F + tx * 4];
        float4 w1 = *(const float4*)&ws[(k + 1) * F + tx * 4];
        float4 w2 = *(const float4*)&ws[(k + 2) * F + tx * 4];
        float4 w3 = *(const float4*)&ws[(k + 3) * F + tx * 4];
#pragma unroll
        for (int r = 0; r < 8; r++) {
            float4 xv = *(const float4*)&xs[(ty + 32 * r) * G_XST + k];
            acc[r].x += xv.x * w0.x + xv.y * w1.x + xv.z * w2.x + xv.w * w3.x;
            acc[r].y += xv.x * w0.y + xv.y * w1.y + xv.z * w2.y + xv.w * w3.y;
            acc[r].z += xv.x * w0.z + xv.y * w1.z + xv.z * w2.z + xv.w * w3.z;
            acc[r].w += xv.x * w0.w + xv.y * w1.w + xv.z * w2.w + xv.w * w3.w;
        }
    }
#pragma unroll
    for (int r = 0; r < 8; r++) {
        const int row = row0 + ty + 32 * r;
        if (row < N) *(float4*)&Y[(size_t)row * F + tx * 4] = acc[r];
    }
}

// ---------------------------------------------------------------------------
// float4 CSR gather: warp per dst row; lane = (sub-row r = lane/8, quad q = lane%8).
// MODE 0: dst = scale*sum   MODE 1: dst = relu(scale*sum + bias)
// ---------------------------------------------------------------------------
template <int MODE>
__global__ void gather_kernel(const int* __restrict__ off,
                              const int* __restrict__ adj,
                              const float* __restrict__ src,
                              const float* __restrict__ scale,
                              const float* __restrict__ bias,
                              float* __restrict__ dst, int nrows) {
    const int row  = (blockIdx.x * blockDim.x + threadIdx.x) >> 5;
    const int lane = threadIdx.x & 31;
    if (row >= nrows) return;
    const int r = lane >> 3;          // 0..3 sub-row slot
    const int q = lane & 7;           // 0..7 quad

    const int s = off[row], e = off[row + 1];
    float4 a = make_float4(0.f, 0.f, 0.f, 0.f);
    int j = s;
    for (; j + 8 <= e; j += 8) {
        int m0 = adj[j + r];
        int m1 = adj[j + 4 + r];
        float4 v0 = *(const float4*)(src + (size_t)m0 * D_HID + q * 4);
        float4 v1 = *(const float4*)(src + (size_t)m1 * D_HID + q * 4);
        a.x += v0.x + v1.x; a.y += v0.y + v1.y;
        a.z += v0.z + v1.z; a.w += v0.w + v1.w;
    }
    for (; j < e; j += 4) {
        if (j + r < e) {
            int m = adj[j + r];
            float4 v = *(const float4*)(src + (size_t)m * D_HID + q * 4);
            a.x += v.x; a.y += v.y; a.z += v.z; a.w += v.w;
        }
    }
#pragma unroll
    for (int o = 8; o <= 16; o <<= 1) {
        a.x += __shfl_xor_sync(0xffffffffu, a.x, o);
        a.y += __shfl_xor_sync(0xffffffffu, a.y, o);
        a.z += __shfl_xor_sync(0xffffffffu, a.z, o);
        a.w += __shfl_xor_sync(0xffffffffu, a.w, o);
    }

    if (r == 0) {
        const float f = scale[row];
        if (MODE == 0) {
            a.x *= f; a.y *= f; a.z *= f; a.w *= f;
        } else {
            float4 bb = *(const float4*)(bias + q * 4);
            a.x = fmaxf(a.x * f + bb.x, 0.f);
            a.y = fmaxf(a.y * f + bb.y, 0.f);
            a.z = fmaxf(a.z * f + bb.z, 0.f);
            a.w = fmaxf(a.w * f + bb.w, 0.f);
        }
        *(float4*)(dst + (size_t)row * D_HID + q * 4) = a;
    }
}

// ---------------------------------------------------------------------------
// Fused final: float4 node-gather + @W2 [32,40] + b2 + log_softmax.
// ---------------------------------------------------------------------------
__global__ void gather_w2_logsoftmax(const int* __restrict__ off,
                                     const int* __restrict__ adj,
                                     const float* __restrict__ src,
                                     const float* __restrict__ dinv,
                                     const float* __restrict__ W2,
                                     const float* __restrict__ b2,
                                     float* __restrict__ out, int nrows) {
    __shared__ float w2s[D_HID * N_CLASSES];
    __shared__ float b2s[N_CLASSES];
    {
        const int t = threadIdx.x;
        for (int i = t; i < D_HID * N_CLASSES; i += blockDim.x) w2s[i] = W2[i];
        if (t < N_CLASSES) b2s[t] = b2[t];
    }
    __syncthreads();

    const int row  = (blockIdx.x * blockDim.x + threadIdx.x) >> 5;
    const int lane = threadIdx.x & 31;
    if (row >= nrows) return;
    const int r = lane >> 3;
    const int q = lane & 7;

    const int s = off[row], e = off[row + 1];
    float4 a = make_float4(0.f, 0.f, 0.f, 0.f);
    int j = s;
    for (; j + 8 <= e; j += 8) {
        int m0 = adj[j + r];
        int m1 = adj[j + 4 + r];
        float4 v0 = *(const float4*)(src + (size_t)m0 * D_HID + q * 4);
        float4 v1 = *(const float4*)(src + (size_t)m1 * D_HID + q * 4);
        a.x += v0.x + v1.x; a.y += v0.y + v1.y;
        a.z += v0.z + v1.z; a.w += v0.w + v1.w;
    }
    for (; j < e; j += 4) {
        if (j + r < e) {
            int m = adj[j + r];
            float4 v = *(const float4*)(src + (size_t)m * D_HID + q * 4);
            a.x += v.x; a.y += v.y; a.z += v.z; a.w += v.w;
        }
    }
#pragma unroll
    for (int o = 8; o <= 16; o <<= 1) {
        a.x += __shfl_xor_sync(0xffffffffu, a.x, o);
        a.y += __shfl_xor_sync(0xffffffffu, a.y, o);
        a.z += __shfl_xor_sync(0xffffffffu, a.z, o);
        a.w += __shfl_xor_sync(0xffffffffu, a.w, o);
    }

    const float di = dinv[row];
    a.x *= di; a.y *= di; a.z *= di; a.w *= di;
    // feature k lives on lane q = k>>2 (all r replicas agree), component k&3.

    float z0 = 0.f, z1 = 0.f;
#pragma unroll
    for (int k = 0; k < D_HID; k++) {
        float comp = ((k & 3) == 0) ? a.x : ((k & 3) == 1) ? a.y
                    : ((k & 3) == 2) ? a.z : a.w;
        float ak = __shfl_sync(0xffffffffu, comp, k >> 2);
        z0 += ak * w2s[k * N_CLASSES + lane];
        if (lane < N_CLASSES - 32) z1 += ak * w2s[k * N_CLASSES + 32 + lane];
    }
    z0 += b2s[lane];
    z1 = (lane < N_CLASSES - 32) ? (z1 + b2s[32 + lane]) : -1e30f;

    float m = fmaxf(z0, z1);
#pragma unroll
    for (int o = 16; o; o >>= 1) m = fmaxf(m, __shfl_xor_sync(0xffffffffu, m, o));
    float ex = __expf(z0 - m) + ((lane < N_CLASSES - 32) ? __expf(z1 - m) : 0.f);
#pragma unroll
    for (int o = 16; o; o >>= 1) ex += __shfl_xor_sync(0xffffffffu, ex, o);
    const float lse = __logf(ex) + m;

    out[(size_t)row * N_CLASSES + lane] = z0 - lse;
    if (lane < N_CLASSES - 32)
        out[(size_t)row * N_CLASSES + 32 + lane] = z1 - lse;
}

// ---------------------------------------------------------------------------
// Launch
// ---------------------------------------------------------------------------
extern "C" void kernel_launch(void* const* d_in, const int* in_sizes, int n_in,
                              void* d_out, int out_size) {
    const float* x    = (const float*)d_in[0];
    const int*   nidx = (const int*)d_in[1];
    const int*   eidx = (const int*)d_in[2];
    const float* W1   = (const float*)d_in[3];
    const float* b1   = (const float*)d_in[4];
    const float* W2   = (const float*)d_in[5];
    const float* b2   = (const float*)d_in[6];
    float* out = (float*)d_out;

    float *xw, *ef, *h1, *dinv, *binv;
    int *cnt_n, *cnt_e, *off_n, *off_e, *adj_n, *adj_e, *rank_n, *rank_e, *aux_n, *aux_e;
    cudaGetSymbolAddress((void**)&xw,     g_xw);
    cudaGetSymbolAddress((void**)&ef,     g_ef);
    cudaGetSymbolAddress((void**)&h1,     g_h1);
    cudaGetSymbolAddress((void**)&dinv,   g_dinv);
    cudaGetSymbolAddress((void**)&binv,   g_binv);
    cudaGetSymbolAddress((void**)&cnt_n,  g_cnt_n);
    cudaGetSymbolAddress((void**)&cnt_e,  g_cnt_e);
    cudaGetSymbolAddress((void**)&off_n,  g_off_n);
    cudaGetSymbolAddress((void**)&off_e,  g_off_e);
    cudaGetSymbolAddress((void**)&adj_n,  g_adj_n);
    cudaGetSymbolAddress((void**)&adj_e,  g_adj_e);
    cudaGetSymbolAddress((void**)&rank_n, g_rank_n);
    cudaGetSymbolAddress((void**)&rank_e, g_rank_e);
    cudaGetSymbolAddress((void**)&aux_n,  g_aux_n);
    cudaGetSymbolAddress((void**)&aux_e,  g_aux_e);

    cudaFuncSetAttribute(gemm1_kernel,
                         cudaFuncAttributeMaxDynamicSharedMemorySize, G_SMEM);

    // ---- degrees + per-pair ranks ----
    cudaMemsetAsync(cnt_n, 0, N_NODES * sizeof(int));
    cudaMemsetAsync(cnt_e, 0, N_EDGES * sizeof(int));
    degree_rank_kernel<<<(N_INC + 255) / 256, 256>>>(nidx, eidx, cnt_n, cnt_e,
                                                     rank_n, rank_e, N_INC);

    // ---- CSR build: combined scans (invert fused into scan_block2) ----
    scan_block2<<<NB_N + NB_E, 1024>>>(cnt_n, off_n, aux_n, dinv,
                                       cnt_e, off_e, aux_e, binv);
    scan_aux2<<<1, 128>>>(aux_n, aux_e);
    gemm1_kernel<<<(N_NODES + G_TR - 1) / G_TR, dim3(8, 32), G_SMEM>>>(x, W1, xw, N_NODES);  // launch #6 for ncu -s 5
    scan_add2<<<NB_N + NB_E, 1024>>>(off_n, aux_n, off_e, aux_e);
    fill_csr<<<(N_INC + 255) / 256, 256>>>(nidx, eidx, off_n, off_e,
                                           rank_n, rank_e, adj_n, adj_e, N_INC);

    // ---- layer 1: h1 = relu(Dinv H Binv H^T (x W1) + b1) ----
    gather_kernel<0><<<(N_EDGES + 7) / 8, 256>>>(off_e, adj_e, xw, binv, nullptr, ef, N_EDGES);
    gather_kernel<1><<<(N_NODES + 7) / 8, 256>>>(off_n, adj_n, ef, dinv, b1, h1, N_NODES);

    // ---- layer 2 (aggregate in hidden space; W2 applied post-aggregation) ----
    gather_kernel<0><<<(N_EDGES + 7) / 8, 256>>>(off_e, adj_e, h1, binv, nullptr, ef, N_EDGES);
    gather_w2_logsoftmax<<<(N_NODES + 7) / 8, 256>>>(off_n, adj_n, ef, dinv, W2, b2, out, N_NODES);
}

// round 11
// speedup vs baseline: 1.5628x; 1.0474x over previous
#include <cuda_runtime.h>
#include <cuda_fp16.h>
#include <cstddef>
#include <cstdint>

#define N_NODES   100000
#define N_EDGES   50000
#define N_INC     3200000
#define D_IN      128
#define D_HID     32
#define N_CLASSES 40

// ---------------------------------------------------------------------------
// Scratch (static device globals). Intermediate feature tables in fp16.
// ---------------------------------------------------------------------------
__device__ __half g_xw[(size_t)N_NODES * D_HID];  // X@W1        (fp16)
__device__ __half g_ef[(size_t)N_EDGES * D_HID];  // edge feats  (fp16)
__device__ __half g_h1[(size_t)N_NODES * D_HID];  // hidden      (fp16)
__device__ float g_dinv[N_NODES];
__device__ float g_binv[N_EDGES];

__device__ int g_cnt_n[N_NODES];
__device__ int g_cnt_e[N_EDGES];
__device__ int g_off_n[N_NODES + 1];
__device__ int g_off_e[N_EDGES + 1];
__device__ int g_adj_n[N_INC];
__device__ int g_adj_e[N_INC];
__device__ int g_rank_n[N_INC];
__device__ int g_rank_e[N_INC];
__device__ int g_aux_n[128];
__device__ int g_aux_e[128];

#define NB_N ((N_NODES + 1023) / 1024)   // 98
#define NB_E ((N_EDGES + 1023) / 1024)   // 49

// ---------------------------------------------------------------------------
// Degree counting + per-pair rank capture
// ---------------------------------------------------------------------------
__global__ void degree_rank_kernel(const int* __restrict__ nidx,
                                   const int* __restrict__ eidx,
                                   int* __restrict__ cn, int* __restrict__ ce,
                                   int* __restrict__ rank_n, int* __restrict__ rank_e,
                                   int n) {
    int i = blockIdx.x * blockDim.x + threadIdx.x;
    if (i < n) {
        rank_n[i] = atomicAdd(cn + nidx[i], 1);
        rank_e[i] = atomicAdd(ce + eidx[i], 1);
    }
}

// ---------------------------------------------------------------------------
// Combined block scan + fused 1/deg
// ---------------------------------------------------------------------------
__global__ void scan_block2(const int* __restrict__ cnt_n, int* __restrict__ off_n,
                            int* __restrict__ aux_n, float* __restrict__ dinv,
                            const int* __restrict__ cnt_e, int* __restrict__ off_e,
                            int* __restrict__ aux_e, float* __restrict__ binv) {
    __shared__ int sm[1024];
    const int b = blockIdx.x;
    const int* in;  int* out; int* aux; float* inv; int n; int bb;
    if (b < NB_N) { in = cnt_n; out = off_n; aux = aux_n; inv = dinv; n = N_NODES; bb = b; }
    else          { in = cnt_e; out = off_e; aux = aux_e; inv = binv; n = N_EDGES; bb = b - NB_N; }

    const int tid = threadIdx.x;
    const int i = bb * 1024 + tid;
    int v = (i < n) ? in[i] : 0;
    if (i < n) inv[i] = (v > 0) ? (1.0f / (float)v) : 0.0f;
    sm[tid] = v;
    __syncthreads();
#pragma unroll
    for (int o = 1; o < 1024; o <<= 1) {
        int t = (tid >= o) ? sm[tid - o] : 0;
        __syncthreads();
        sm[tid] += t;
        __syncthreads();
    }
    if (i < n) out[i] = sm[tid] - v;
    if (tid == 1023) aux[bb] = sm[1023];
}

__global__ void scan_aux2(int* __restrict__ aux_n, int* __restrict__ aux_e) {
    __shared__ int sm[128];
    const int t = threadIdx.x;

    int orig = (t < NB_N) ? aux_n[t] : 0;
    sm[t] = orig;
    __syncthreads();
#pragma unroll
    for (int o = 1; o < 128; o <<= 1) {
        int v = (t >= o) ? sm[t - o] : 0;
        __syncthreads();
        sm[t] += v;
        __syncthreads();
    }
    if (t < NB_N) aux_n[t] = sm[t] - orig;
    __syncthreads();

    orig = (t < NB_E) ? aux_e[t] : 0;
    sm[t] = orig;
    __syncthreads();
#pragma unroll
    for (int o = 1; o < 128; o <<= 1) {
        int v = (t >= o) ? sm[t - o] : 0;
        __syncthreads();
        sm[t] += v;
        __syncthreads();
    }
    if (t < NB_E) aux_e[t] = sm[t] - orig;
}

__global__ void scan_add2(int* __restrict__ off_n, const int* __restrict__ aux_n,
                          int* __restrict__ off_e, const int* __restrict__ aux_e) {
    const int b = blockIdx.x;
    if (b < NB_N) {
        int i = b * 1024 + threadIdx.x;
        if (i < N_NODES) off_n[i] += aux_n[b];
        if (i == 0) off_n[N_NODES] = N_INC;
    } else {
        int i = (b - NB_N) * 1024 + threadIdx.x;
        if (i < N_EDGES) off_e[i] += aux_e[b - NB_N];
        if (i == 0) off_e[N_EDGES] = N_INC;
    }
}

// ---------------------------------------------------------------------------
// CSR fill — atomic-free via precomputed ranks
// ---------------------------------------------------------------------------
__global__ void fill_csr(const int* __restrict__ nidx, const int* __restrict__ eidx,
                         const int* __restrict__ off_n, const int* __restrict__ off_e,
                         const int* __restrict__ rank_n, const int* __restrict__ rank_e,
                         int* __restrict__ adj_n, int* __restrict__ adj_e, int n) {
    int i = blockIdx.x * blockDim.x + threadIdx.x;
    if (i < n) {
        int v = nidx[i], e = eidx[i];
        adj_n[__ldg(off_n + v) + rank_n[i]] = e;
        adj_e[__ldg(off_e + e) + rank_e[i]] = v;
    }
}

// ---------------------------------------------------------------------------
// GEMM1: Y[N,32](fp16) = X[N,128] @ W[128,32]. (8,32) block, 256-row tile.
// ---------------------------------------------------------------------------
#define G_TR   256
#define G_XST  (D_IN + 4)
#define G_SMEM ((D_IN * D_HID + G_TR * G_XST) * (int)sizeof(float))  // 151552 B

__global__ void gemm1_kernel(const float* __restrict__ X,
                             const float* __restrict__ W,
                             __half* __restrict__ Y, int N) {
    constexpr int K = D_IN, F = D_HID;
    extern __shared__ float smem[];
    float* ws = smem;
    float* xs = smem + K * F;
    const int tx = threadIdx.x;          // 0..7  (col quad)
    const int ty = threadIdx.y;          // 0..31 (row slot)
    const int tid = ty * 8 + tx;

    for (int i = tid; i < K * F / 4; i += 256)
        ((float4*)ws)[i] = ((const float4*)W)[i];

    const int row0 = blockIdx.x * G_TR;
    for (int i = tid; i < G_TR * (K / 4); i += 256) {
        int r = i >> 5, c = i & 31;
        float4 v = make_float4(0.f, 0.f, 0.f, 0.f);
        if (row0 + r < N) v = ((const float4*)X)[(size_t)(row0 + r) * (K / 4) + c];
        *(float4*)&xs[r * G_XST + c * 4] = v;
    }
    __syncthreads();

    float4 acc[8];
#pragma unroll
    for (int r = 0; r < 8; r++) acc[r] = make_float4(0.f, 0.f, 0.f, 0.f);

#pragma unroll
    for (int k = 0; k < K; k += 4) {
        float4 w0 = *(const float4*)&ws[(k + 0) * F + tx * 4];
        float4 w1 = *(const float4*)&ws[(k + 1) * F + tx * 4];
        float4 w2 = *(const float4*)&ws[(k + 2) * F + tx * 4];
        float4 w3 = *(const float4*)&ws[(k + 3) * F + tx * 4];
#pragma unroll
        for (int r = 0; r < 8; r++) {
            float4 xv = *(const float4*)&xs[(ty + 32 * r) * G_XST + k];
            acc[r].x += xv.x * w0.x + xv.y * w1.x + xv.z * w2.x + xv.w * w3.x;
            acc[r].y += xv.x * w0.y + xv.y * w1.y + xv.z * w2.y + xv.w * w3.y;
            acc[r].z += xv.x * w0.z + xv.y * w1.z + xv.z * w2.z + xv.w * w3.z;
            acc[r].w += xv.x * w0.w + xv.y * w1.w + xv.z * w2.w + xv.w * w3.w;
        }
    }
#pragma unroll
    for (int r = 0; r < 8; r++) {
        const int row = row0 + ty + 32 * r;
        if (row < N) {
            __half2 h0 = __float22half2_rn(make_float2(acc[r].x, acc[r].y));
            __half2 h1 = __float22half2_rn(make_float2(acc[r].z, acc[r].w));
            uint2 pk = make_uint2(*(uint32_t*)&h0, *(uint32_t*)&h1);
            *(uint2*)(Y + (size_t)row * F + tx * 4) = pk;
        }
    }
}

// ---------------------------------------------------------------------------
// fp16 CSR gather: warp per dst row. Row = 32 halves = 64B.
// lane -> (member slot r = lane>>2, quad q = lane&3). 16B load covers 8 feats.
// 16 members per main iteration (2 loads/lane). fp32 accumulate.
// MODE 0: dst = half(scale*sum)   MODE 1: dst = half(relu(scale*sum + bias))
// ---------------------------------------------------------------------------
__device__ __forceinline__ void acc8(float2 a[4], uint4 v) {
    float2 f0 = __half22float2(*(const __half2*)&v.x);
    float2 f1 = __half22float2(*(const __half2*)&v.y);
    float2 f2 = __half22float2(*(const __half2*)&v.z);
    float2 f3 = __half22float2(*(const __half2*)&v.w);
    a[0].x += f0.x; a[0].y += f0.y;
    a[1].x += f1.x; a[1].y += f1.y;
    a[2].x += f2.x; a[2].y += f2.y;
    a[3].x += f3.x; a[3].y += f3.y;
}

template <int MODE>
__global__ void gather_kernel(const int* __restrict__ off,
                              const int* __restrict__ adj,
                              const __half* __restrict__ src,
                              const float* __restrict__ scale,
                              const float* __restrict__ bias,
                              __half* __restrict__ dst, int nrows) {
    const int row  = (blockIdx.x * blockDim.x + threadIdx.x) >> 5;
    const int lane = threadIdx.x & 31;
    if (row >= nrows) return;
    const int r = lane >> 2;          // 0..7 member slot
    const int q = lane & 3;           // 0..3 quad (8 halves)

    const int s = off[row], e = off[row + 1];
    float2 a[4] = {{0.f,0.f},{0.f,0.f},{0.f,0.f},{0.f,0.f}};
    int j = s;
    for (; j + 16 <= e; j += 16) {
        int m0 = adj[j + r];
        int m1 = adj[j + 8 + r];
        uint4 v0 = *(const uint4*)(src + (size_t)m0 * D_HID + q * 8);
        uint4 v1 = *(const uint4*)(src + (size_t)m1 * D_HID + q * 8);
        acc8(a, v0);
        acc8(a, v1);
    }
    for (; j < e; j += 8) {
        if (j + r < e) {
            int m = adj[j + r];
            uint4 v = *(const uint4*)(src + (size_t)m * D_HID + q * 8);
            acc8(a, v);
        }
    }
#pragma unroll
    for (int o = 4; o <= 16; o <<= 1) {
#pragma unroll
        for (int i = 0; i < 4; i++) {
            a[i].x += __shfl_xor_sync(0xffffffffu, a[i].x, o);
            a[i].y += __shfl_xor_sync(0xffffffffu, a[i].y, o);
        }
    }

    if (r == 0) {
        const float f = scale[row];
        uint4 pk;
        if (MODE == 0) {
            __half2 h0 = __float22half2_rn(make_float2(a[0].x * f, a[0].y * f));
            __half2 h1 = __float22half2_rn(make_float2(a[1].x * f, a[1].y * f));
            __half2 h2 = __float22half2_rn(make_float2(a[2].x * f, a[2].y * f));
            __half2 h3 = __float22half2_rn(make_float2(a[3].x * f, a[3].y * f));
            pk = make_uint4(*(uint32_t*)&h0, *(uint32_t*)&h1,
                            *(uint32_t*)&h2, *(uint32_t*)&h3);
        } else {
            float4 b0 = *(const float4*)(bias + q * 8);
            float4 b1 = *(const float4*)(bias + q * 8 + 4);
            float z0 = fmaxf(a[0].x * f + b0.x, 0.f);
            float z1 = fmaxf(a[0].y * f + b0.y, 0.f);
            float z2 = fmaxf(a[1].x * f + b0.z, 0.f);
            float z3 = fmaxf(a[1].y * f + b0.w, 0.f);
            float z4 = fmaxf(a[2].x * f + b1.x, 0.f);
            float z5 = fmaxf(a[2].y * f + b1.y, 0.f);
            float z6 = fmaxf(a[3].x * f + b1.z, 0.f);
            float z7 = fmaxf(a[3].y * f + b1.w, 0.f);
            __half2 h0 = __float22half2_rn(make_float2(z0, z1));
            __half2 h1 = __float22half2_rn(make_float2(z2, z3));
            __half2 h2 = __float22half2_rn(make_float2(z4, z5));
            __half2 h3 = __float22half2_rn(make_float2(z6, z7));
            pk = make_uint4(*(uint32_t*)&h0, *(uint32_t*)&h1,
                            *(uint32_t*)&h2, *(uint32_t*)&h3);
        }
        *(uint4*)(dst + (size_t)row * D_HID + q * 8) = pk;
    }
}

// ---------------------------------------------------------------------------
// Fused final: fp16 node-gather + @W2 [32,40] + b2 + log_softmax (fp32 out).
// ---------------------------------------------------------------------------
__global__ void gather_w2_logsoftmax(const int* __restrict__ off,
                                     const int* __restrict__ adj,
                                     const __half* __restrict__ src,
                                     const float* __restrict__ dinv,
                                     const float* __restrict__ W2,
                                     const float* __restrict__ b2,
                                     float* __restrict__ out, int nrows) {
    __shared__ float w2s[D_HID * N_CLASSES];
    __shared__ float b2s[N_CLASSES];
    {
        const int t = threadIdx.x;
        for (int i = t; i < D_HID * N_CLASSES; i += blockDim.x) w2s[i] = W2[i];
        if (t < N_CLASSES) b2s[t] = b2[t];
    }
    __syncthreads();

    const int row  = (blockIdx.x * blockDim.x + threadIdx.x) >> 5;
    const int lane = threadIdx.x & 31;
    if (row >= nrows) return;
    const int r = lane >> 2;
    const int q = lane & 3;

    const int s = off[row], e = off[row + 1];
    float2 a[4] = {{0.f,0.f},{0.f,0.f},{0.f,0.f},{0.f,0.f}};
    int j = s;
    for (; j + 16 <= e; j += 16) {
        int m0 = adj[j + r];
        int m1 = adj[j + 8 + r];
        uint4 v0 = *(const uint4*)(src + (size_t)m0 * D_HID + q * 8);
        uint4 v1 = *(const uint4*)(src + (size_t)m1 * D_HID + q * 8);
        acc8(a, v0);
        acc8(a, v1);
    }
    for (; j < e; j += 8) {
        if (j + r < e) {
            int m = adj[j + r];
            uint4 v = *(const uint4*)(src + (size_t)m * D_HID + q * 8);
            acc8(a, v);
        }
    }
#pragma unroll
    for (int o = 4; o <= 16; o <<= 1) {
#pragma unroll
        for (int i = 0; i < 4; i++) {
            a[i].x += __shfl_xor_sync(0xffffffffu, a[i].x, o);
            a[i].y += __shfl_xor_sync(0xffffffffu, a[i].y, o);
        }
    }

    const float di = dinv[row];
#pragma unroll
    for (int i = 0; i < 4; i++) { a[i].x *= di; a[i].y *= di; }
    // feature k: owner lane q = k>>3 (r=0 replica), comp idx = k&7 -> a[(k&7)>>1].x/.y

    float z0 = 0.f, z1 = 0.f;
#pragma unroll
    for (int k = 0; k < D_HID; k++) {
        const int idx = k & 7;
        float comp = (idx & 1) ? a[idx >> 1].y : a[idx >> 1].x;
        float ak = __shfl_sync(0xffffffffu, comp, k >> 3);
        z0 += ak * w2s[k * N_CLASSES + lane];
        if (lane < N_CLASSES - 32) z1 += ak * w2s[k * N_CLASSES + 32 + lane];
    }
    z0 += b2s[lane];
    z1 = (lane < N_CLASSES - 32) ? (z1 + b2s[32 + lane]) : -1e30f;

    float m = fmaxf(z0, z1);
#pragma unroll
    for (int o = 16; o; o >>= 1) m = fmaxf(m, __shfl_xor_sync(0xffffffffu, m, o));
    float ex = __expf(z0 - m) + ((lane < N_CLASSES - 32) ? __expf(z1 - m) : 0.f);
#pragma unroll
    for (int o = 16; o; o >>= 1) ex += __shfl_xor_sync(0xffffffffu, ex, o);
    const float lse = __logf(ex) + m;

    out[(size_t)row * N_CLASSES + lane] = z0 - lse;
    if (lane < N_CLASSES - 32)
        out[(size_t)row * N_CLASSES + 32 + lane] = z1 - lse;
}

// ---------------------------------------------------------------------------
// Launch
// ---------------------------------------------------------------------------
extern "C" void kernel_launch(void* const* d_in, const int* in_sizes, int n_in,
                              void* d_out, int out_size) {
    const float* x    = (const float*)d_in[0];
    const int*   nidx = (const int*)d_in[1];
    const int*   eidx = (const int*)d_in[2];
    const float* W1   = (const float*)d_in[3];
    const float* b1   = (const float*)d_in[4];
    const float* W2   = (const float*)d_in[5];
    const float* b2   = (const float*)d_in[6];
    float* out = (float*)d_out;

    __half *xw, *ef, *h1;
    float *dinv, *binv;
    int *cnt_n, *cnt_e, *off_n, *off_e, *adj_n, *adj_e, *rank_n, *rank_e, *aux_n, *aux_e;
    cudaGetSymbolAddress((void**)&xw,     g_xw);
    cudaGetSymbolAddress((void**)&ef,     g_ef);
    cudaGetSymbolAddress((void**)&h1,     g_h1);
    cudaGetSymbolAddress((void**)&dinv,   g_dinv);
    cudaGetSymbolAddress((void**)&binv,   g_binv);
    cudaGetSymbolAddress((void**)&cnt_n,  g_cnt_n);
    cudaGetSymbolAddress((void**)&cnt_e,  g_cnt_e);
    cudaGetSymbolAddress((void**)&off_n,  g_off_n);
    cudaGetSymbolAddress((void**)&off_e,  g_off_e);
    cudaGetSymbolAddress((void**)&adj_n,  g_adj_n);
    cudaGetSymbolAddress((void**)&adj_e,  g_adj_e);
    cudaGetSymbolAddress((void**)&rank_n, g_rank_n);
    cudaGetSymbolAddress((void**)&rank_e, g_rank_e);
    cudaGetSymbolAddress((void**)&aux_n,  g_aux_n);
    cudaGetSymbolAddress((void**)&aux_e,  g_aux_e);

    cudaFuncSetAttribute(gemm1_kernel,
                         cudaFuncAttributeMaxDynamicSharedMemorySize, G_SMEM);

    // ---- degrees + per-pair ranks ----
    cudaMemsetAsync(cnt_n, 0, N_NODES * sizeof(int));
    cudaMemsetAsync(cnt_e, 0, N_EDGES * sizeof(int));
    degree_rank_kernel<<<(N_INC + 255) / 256, 256>>>(nidx, eidx, cnt_n, cnt_e,
                                                     rank_n, rank_e, N_INC);

    // ---- CSR build ----
    scan_block2<<<NB_N + NB_E, 1024>>>(cnt_n, off_n, aux_n, dinv,
                                       cnt_e, off_e, aux_e, binv);
    scan_aux2<<<1, 128>>>(aux_n, aux_e);
    gemm1_kernel<<<(N_NODES + G_TR - 1) / G_TR, dim3(8, 32), G_SMEM>>>(x, W1, xw, N_NODES);  // launch #6 for ncu -s 5
    scan_add2<<<NB_N + NB_E, 1024>>>(off_n, aux_n, off_e, aux_e);
    fill_csr<<<(N_INC + 255) / 256, 256>>>(nidx, eidx, off_n, off_e,
                                           rank_n, rank_e, adj_n, adj_e, N_INC);

    // ---- layer 1 ----
    gather_kernel<0><<<(N_EDGES + 7) / 8, 256>>>(off_e, adj_e, xw, binv, nullptr, ef, N_EDGES);
    gather_kernel<1><<<(N_NODES + 7) / 8, 256>>>(off_n, adj_n, ef, dinv, b1, h1, N_NODES);

    // ---- layer 2 (aggregate in hidden space; W2 post-aggregation) ----
    gather_kernel<0><<<(N_EDGES + 7) / 8, 256>>>(off_e, adj_e, h1, binv, nullptr, ef, N_EDGES);
    gather_w2_logsoftmax<<<(N_NODES + 7) / 8, 256>>>(off_n, adj_n, ef, dinv, W2, b2, out, N_NODES);
}

// round 13
// speedup vs baseline: 1.7626x; 1.1278x over previous
#include <cuda_runtime.h>
#include <cuda_fp16.h>
#include <mma.h>
#include <cstddef>
#include <cstdint>

using namespace nvcuda;

#define N_NODES   100000
#define N_EDGES   50000
#define N_INC     3200000
#define D_IN      128
#define D_HID     32
#define N_CLASSES 40

// ---------------------------------------------------------------------------
// Scratch (static device globals). Intermediate feature tables in fp16.
// ---------------------------------------------------------------------------
__device__ __half g_xw[(size_t)N_NODES * D_HID];
__device__ __half g_ef[(size_t)N_EDGES * D_HID];
__device__ __half g_h1[(size_t)N_NODES * D_HID];
__device__ float g_dinv[N_NODES];
__device__ float g_binv[N_EDGES];

__device__ int g_cnt_n[N_NODES];
__device__ int g_cnt_e[N_EDGES];
__device__ int g_off_n[N_NODES + 1];
__device__ int g_off_e[N_EDGES + 1];
__device__ int g_adj_n[N_INC];
__device__ int g_adj_e[N_INC];
__device__ unsigned short g_rank_n[N_INC];
__device__ unsigned short g_rank_e[N_INC];
__device__ int g_aux_n[128];
__device__ int g_aux_e[128];

#define NB_N ((N_NODES + 1023) / 1024)   // 98
#define NB_E ((N_EDGES + 1023) / 1024)   // 49

// ---------------------------------------------------------------------------
// GEMM1 (wmma tensor-core): Y[N,32](fp16) = X[N,128](fp32->fp16) @ W1(fp16).
// 256 threads (8 warps); 256-row tile. Warp w: rows 32w..32w+31 (2 M-frags),
// full N=32 (2 N-frags). Also zeroes the degree counters (runs first).
// smem: ws 8KB + xs 68KB (aliased by 32KB float out-stage after compute).
// ---------------------------------------------------------------------------
#define G_TR   256
#define G_XLD  136                                     // halves/row, mult of 8
#define G_SMEM (D_IN * D_HID * 2 + G_TR * G_XLD * 2)   // 8192 + 69632 = 77824

__global__ void gemm1_kernel(const float* __restrict__ X,
                             const float* __restrict__ W,
                             __half* __restrict__ Y, int N,
                             int* __restrict__ cn, int* __restrict__ ce) {
    extern __shared__ __align__(16) char smemraw[];
    __half* ws = (__half*)smemraw;                     // 128x32
    __half* xs = (__half*)(smemraw + 8192);            // 256x136
    float*  ys = (float*)(smemraw + 8192);             // 256x32 (alias, post-compute)
    const int tid  = threadIdx.x;
    const int warp = tid >> 5;

    // zero degree counters (this kernel launches first)
    for (int i = blockIdx.x * blockDim.x + tid; i < N_NODES; i += gridDim.x * blockDim.x)
        cn[i] = 0;
    for (int i = blockIdx.x * blockDim.x + tid; i < N_EDGES; i += gridDim.x * blockDim.x)
        ce[i] = 0;

    // stage W1 -> half
    for (int i = tid; i < (D_IN * D_HID) / 4; i += 256) {
        float4 w = ((const float4*)W)[i];
        __half2 h0 = __float22half2_rn(make_float2(w.x, w.y));
        __half2 h1 = __float22half2_rn(make_float2(w.z, w.w));
        *(uint2*)(ws + i * 4) = make_uint2(*(uint32_t*)&h0, *(uint32_t*)&h1);
    }
    // stage X tile -> half
    const int row0 = blockIdx.x * G_TR;
    for (int i = tid; i < G_TR * (D_IN / 4); i += 256) {
        int r = i >> 5, c = i & 31;
        float4 v = make_float4(0.f, 0.f, 0.f, 0.f);
        if (row0 + r < N) v = ((const float4*)X)[(size_t)(row0 + r) * (D_IN / 4) + c];
        __half2 h0 = __float22half2_rn(make_float2(v.x, v.y));
        __half2 h1 = __float22half2_rn(make_float2(v.z, v.w));
        *(uint2*)(xs + r * G_XLD + c * 4) = make_uint2(*(uint32_t*)&h0, *(uint32_t*)&h1);
    }
    __syncthreads();

    wmma::fragment<wmma::accumulator, 16, 16, 16, float> acc00, acc01, acc10, acc11;
    wmma::fill_fragment(acc00, 0.f); wmma::fill_fragment(acc01, 0.f);
    wmma::fill_fragment(acc10, 0.f); wmma::fill_fragment(acc11, 0.f);

    const __half* a0 = xs + (32 * warp) * G_XLD;
    const __half* a1 = xs + (32 * warp + 16) * G_XLD;
#pragma unroll
    for (int k = 0; k < D_IN; k += 16) {
        wmma::fragment<wmma::matrix_a, 16, 16, 16, __half, wmma::row_major> fa0, fa1;
        wmma::fragment<wmma::matrix_b, 16, 16, 16, __half, wmma::row_major> fb0, fb1;
        wmma::load_matrix_sync(fa0, a0 + k, G_XLD);
        wmma::load_matrix_sync(fa1, a1 + k, G_XLD);
        wmma::load_matrix_sync(fb0, ws + k * D_HID, D_HID);
        wmma::load_matrix_sync(fb1, ws + k * D_HID + 16, D_HID);
        wmma::mma_sync(acc00, fa0, fb0, acc00);
        wmma::mma_sync(acc01, fa0, fb1, acc01);
        wmma::mma_sync(acc10, fa1, fb0, acc10);
        wmma::mma_sync(acc11, fa1, fb1, acc11);
    }
    __syncthreads();   // done reading xs; safe to alias as ys

    wmma::store_matrix_sync(ys + (32 * warp) * 32,           acc00, 32, wmma::mem_row_major);
    wmma::store_matrix_sync(ys + (32 * warp) * 32 + 16,      acc01, 32, wmma::mem_row_major);
    wmma::store_matrix_sync(ys + (32 * warp + 16) * 32,      acc10, 32, wmma::mem_row_major);
    wmma::store_matrix_sync(ys + (32 * warp + 16) * 32 + 16, acc11, 32, wmma::mem_row_major);
    __syncthreads();

    // convert + write out
    for (int i = tid; i < G_TR * 8; i += 256) {        // 8 quads/row
        int r = i >> 3, c4 = i & 7;
        const int row = row0 + r;
        if (row < N) {
            float4 v = *(const float4*)(ys + r * 32 + c4 * 4);
            __half2 h0 = __float22half2_rn(make_float2(v.x, v.y));
            __half2 h1 = __float22half2_rn(make_float2(v.z, v.w));
            *(uint2*)(Y + (size_t)row * D_HID + c4 * 4) =
                make_uint2(*(uint32_t*)&h0, *(uint32_t*)&h1);
        }
    }
}

// ---------------------------------------------------------------------------
// Degree counting + per-pair rank capture (u16 ranks)
// ---------------------------------------------------------------------------
__global__ void degree_rank_kernel(const int* __restrict__ nidx,
                                   const int* __restrict__ eidx,
                                   int* __restrict__ cn, int* __restrict__ ce,
                                   unsigned short* __restrict__ rank_n,
                                   unsigned short* __restrict__ rank_e, int n) {
    int i = blockIdx.x * blockDim.x + threadIdx.x;
    if (i < n) {
        rank_n[i] = (unsigned short)atomicAdd(cn + nidx[i], 1);
        rank_e[i] = (unsigned short)atomicAdd(ce + eidx[i], 1);
    }
}

// ---------------------------------------------------------------------------
// Combined block scan + fused 1/deg
// ---------------------------------------------------------------------------
__global__ void scan_block2(const int* __restrict__ cnt_n, int* __restrict__ off_n,
                            int* __restrict__ aux_n, float* __restrict__ dinv,
                            const int* __restrict__ cnt_e, int* __restrict__ off_e,
                            int* __restrict__ aux_e, float* __restrict__ binv) {
    __shared__ int sm[1024];
    const int b = blockIdx.x;
    const int* in;  int* out; int* aux; float* inv; int n; int bb;
    if (b < NB_N) { in = cnt_n; out = off_n; aux = aux_n; inv = dinv; n = N_NODES; bb = b; }
    else          { in = cnt_e; out = off_e; aux = aux_e; inv = binv; n = N_EDGES; bb = b - NB_N; }

    const int tid = threadIdx.x;
    const int i = bb * 1024 + tid;
    int v = (i < n) ? in[i] : 0;
    if (i < n) inv[i] = (v > 0) ? (1.0f / (float)v) : 0.0f;
    sm[tid] = v;
    __syncthreads();
#pragma unroll
    for (int o = 1; o < 1024; o <<= 1) {
        int t = (tid >= o) ? sm[tid - o] : 0;
        __syncthreads();
        sm[tid] += t;
        __syncthreads();
    }
    if (i < n) out[i] = sm[tid] - v;
    if (tid == 1023) aux[bb] = sm[1023];
}

// Add-pass with INLINE aux scan (each block redundantly scans its aux array).
__global__ void scan_add2(int* __restrict__ off_n, const int* __restrict__ aux_n,
                          int* __restrict__ off_e, const int* __restrict__ aux_e) {
    __shared__ int sm[128];
    const int b = blockIdx.x;
    const int t = threadIdx.x;
    const int* aux; int* off; int n; int bb; int nb;
    if (b < NB_N) { aux = aux_n; off = off_n; n = N_NODES; bb = b; nb = NB_N; }
    else          { aux = aux_e; off = off_e; n = N_EDGES; bb = b - NB_N; nb = NB_E; }

    if (t < 128) sm[t] = (t < nb) ? aux[t] : 0;
    __syncthreads();
#pragma unroll
    for (int o = 1; o < 128; o <<= 1) {
        int v = (t < 128 && t >= o) ? sm[t - o] : 0;
        __syncthreads();
        if (t < 128) sm[t] += v;
        __syncthreads();
    }
    const int add = (bb == 0) ? 0 : sm[bb - 1];     // exclusive prefix
    const int i = bb * 1024 + t;
    if (i < n) off[i] += add;
    if (i == 0 && bb == 0) off[n] = N_INC;
}

// ---------------------------------------------------------------------------
// CSR fill — atomic-free via precomputed u16 ranks
// ---------------------------------------------------------------------------
__global__ void fill_csr(const int* __restrict__ nidx, const int* __restrict__ eidx,
                         const int* __restrict__ off_n, const int* __restrict__ off_e,
                         const unsigned short* __restrict__ rank_n,
                         const unsigned short* __restrict__ rank_e,
                         int* __restrict__ adj_n, int* __restrict__ adj_e, int n) {
    int i = blockIdx.x * blockDim.x + threadIdx.x;
    if (i < n) {
        int v = nidx[i], e = eidx[i];
        adj_n[__ldg(off_n + v) + (int)rank_n[i]] = e;
        adj_e[__ldg(off_e + e) + (int)rank_e[i]] = v;
    }
}

// ---------------------------------------------------------------------------
// fp16 CSR gather (unchanged from validated R11 version)
// ---------------------------------------------------------------------------
__device__ __forceinline__ void acc8(float2 a[4], uint4 v) {
    float2 f0 = __half22float2(*(const __half2*)&v.x);
    float2 f1 = __half22float2(*(const __half2*)&v.y);
    float2 f2 = __half22float2(*(const __half2*)&v.z);
    float2 f3 = __half22float2(*(const __half2*)&v.w);
    a[0].x += f0.x; a[0].y += f0.y;
    a[1].x += f1.x; a[1].y += f1.y;
    a[2].x += f2.x; a[2].y += f2.y;
    a[3].x += f3.x; a[3].y += f3.y;
}

template <int MODE>
__global__ void gather_kernel(const int* __restrict__ off,
                              const int* __restrict__ adj,
                              const __half* __restrict__ src,
                              const float* __restrict__ scale,
                              const float* __restrict__ bias,
                              __half* __restrict__ dst, int nrows) {
    const int row  = (blockIdx.x * blockDim.x + threadIdx.x) >> 5;
    const int lane = threadIdx.x & 31;
    if (row >= nrows) return;
    const int r = lane >> 2;
    const int q = lane & 3;

    const int s = off[row], e = off[row + 1];
    float2 a[4] = {{0.f,0.f},{0.f,0.f},{0.f,0.f},{0.f,0.f}};
    int j = s;
    for (; j + 16 <= e; j += 16) {
        int m0 = adj[j + r];
        int m1 = adj[j + 8 + r];
        uint4 v0 = *(const uint4*)(src + (size_t)m0 * D_HID + q * 8);
        uint4 v1 = *(const uint4*)(src + (size_t)m1 * D_HID + q * 8);
        acc8(a, v0);
        acc8(a, v1);
    }
    for (; j < e; j += 8) {
        if (j + r < e) {
            int m = adj[j + r];
            uint4 v = *(const uint4*)(src + (size_t)m * D_HID + q * 8);
            acc8(a, v);
        }
    }
#pragma unroll
    for (int o = 4; o <= 16; o <<= 1) {
#pragma unroll
        for (int i = 0; i < 4; i++) {
            a[i].x += __shfl_xor_sync(0xffffffffu, a[i].x, o);
            a[i].y += __shfl_xor_sync(0xffffffffu, a[i].y, o);
        }
    }

    if (r == 0) {
        const float f = scale[row];
        uint4 pk;
        if (MODE == 0) {
            __half2 h0 = __float22half2_rn(make_float2(a[0].x * f, a[0].y * f));
            __half2 h1 = __float22half2_rn(make_float2(a[1].x * f, a[1].y * f));
            __half2 h2 = __float22half2_rn(make_float2(a[2].x * f, a[2].y * f));
            __half2 h3 = __float22half2_rn(make_float2(a[3].x * f, a[3].y * f));
            pk = make_uint4(*(uint32_t*)&h0, *(uint32_t*)&h1,
                            *(uint32_t*)&h2, *(uint32_t*)&h3);
        } else {
            float4 b0 = *(const float4*)(bias + q * 8);
            float4 b1 = *(const float4*)(bias + q * 8 + 4);
            float z0 = fmaxf(a[0].x * f + b0.x, 0.f);
            float z1 = fmaxf(a[0].y * f + b0.y, 0.f);
            float z2 = fmaxf(a[1].x * f + b0.z, 0.f);
            float z3 = fmaxf(a[1].y * f + b0.w, 0.f);
            float z4 = fmaxf(a[2].x * f + b1.x, 0.f);
            float z5 = fmaxf(a[2].y * f + b1.y, 0.f);
            float z6 = fmaxf(a[3].x * f + b1.z, 0.f);
            float z7 = fmaxf(a[3].y * f + b1.w, 0.f);
            __half2 h0 = __float22half2_rn(make_float2(z0, z1));
            __half2 h1 = __float22half2_rn(make_float2(z2, z3));
            __half2 h2 = __float22half2_rn(make_float2(z4, z5));
            __half2 h3 = __float22half2_rn(make_float2(z6, z7));
            pk = make_uint4(*(uint32_t*)&h0, *(uint32_t*)&h1,
                            *(uint32_t*)&h2, *(uint32_t*)&h3);
        }
        *(uint4*)(dst + (size_t)row * D_HID + q * 8) = pk;
    }
}

// ---------------------------------------------------------------------------
// Fused final: fp16 node-gather + @W2 [32,40] + b2 + log_softmax (fp32 out).
// ---------------------------------------------------------------------------
__global__ void gather_w2_logsoftmax(const int* __restrict__ off,
                                     const int* __restrict__ adj,
                                     const __half* __restrict__ src,
                                     const float* __restrict__ dinv,
                                     const float* __restrict__ W2,
                                     const float* __restrict__ b2,
                                     float* __restrict__ out, int nrows) {
    __shared__ float w2s[D_HID * N_CLASSES];
    __shared__ float b2s[N_CLASSES];
    {
        const int t = threadIdx.x;
        for (int i = t; i < D_HID * N_CLASSES; i += blockDim.x) w2s[i] = W2[i];
        if (t < N_CLASSES) b2s[t] = b2[t];
    }
    __syncthreads();

    const int row  = (blockIdx.x * blockDim.x + threadIdx.x) >> 5;
    const int lane = threadIdx.x & 31;
    if (row >= nrows) return;
    const int r = lane >> 2;
    const int q = lane & 3;

    const int s = off[row], e = off[row + 1];
    float2 a[4] = {{0.f,0.f},{0.f,0.f},{0.f,0.f},{0.f,0.f}};
    int j = s;
    for (; j + 16 <= e; j += 16) {
        int m0 = adj[j + r];
        int m1 = adj[j + 8 + r];
        uint4 v0 = *(const uint4*)(src + (size_t)m0 * D_HID + q * 8);
        uint4 v1 = *(const uint4*)(src + (size_t)m1 * D_HID + q * 8);
        acc8(a, v0);
        acc8(a, v1);
    }
    for (; j < e; j += 8) {
        if (j + r < e) {
            int m = adj[j + r];
            uint4 v = *(const uint4*)(src + (size_t)m * D_HID + q * 8);
            acc8(a, v);
        }
    }
#pragma unroll
    for (int o = 4; o <= 16; o <<= 1) {
#pragma unroll
        for (int i = 0; i < 4; i++) {
            a[i].x += __shfl_xor_sync(0xffffffffu, a[i].x, o);
            a[i].y += __shfl_xor_sync(0xffffffffu, a[i].y, o);
        }
    }

    const float di = dinv[row];
#pragma unroll
    for (int i = 0; i < 4; i++) { a[i].x *= di; a[i].y *= di; }

    float z0 = 0.f, z1 = 0.f;
#pragma unroll
    for (int k = 0; k < D_HID; k++) {
        const int idx = k & 7;
        float comp = (idx & 1) ? a[idx >> 1].y : a[idx >> 1].x;
        float ak = __shfl_sync(0xffffffffu, comp, k >> 3);
        z0 += ak * w2s[k * N_CLASSES + lane];
        if (lane < N_CLASSES - 32) z1 += ak * w2s[k * N_CLASSES + 32 + lane];
    }
    z0 += b2s[lane];
    z1 = (lane < N_CLASSES - 32) ? (z1 + b2s[32 + lane]) : -1e30f;

    float m = fmaxf(z0, z1);
#pragma unroll
    for (int o = 16; o; o >>= 1) m = fmaxf(m, __shfl_xor_sync(0xffffffffu, m, o));
    float ex = __expf(z0 - m) + ((lane < N_CLASSES - 32) ? __expf(z1 - m) : 0.f);
#pragma unroll
    for (int o = 16; o; o >>= 1) ex += __shfl_xor_sync(0xffffffffu, ex, o);
    const float lse = __logf(ex) + m;

    out[(size_t)row * N_CLASSES + lane] = z0 - lse;
    if (lane < N_CLASSES - 32)
        out[(size_t)row * N_CLASSES + 32 + lane] = z1 - lse;
}

// ---------------------------------------------------------------------------
// Launch — 9 kernels; edge gather is launch #6 (ncu -s 5 -c 1 target)
// ---------------------------------------------------------------------------
extern "C" void kernel_launch(void* const* d_in, const int* in_sizes, int n_in,
                              void* d_out, int out_size) {
    const float* x    = (const float*)d_in[0];
    const int*   nidx = (const int*)d_in[1];
    const int*   eidx = (const int*)d_in[2];
    const float* W1   = (const float*)d_in[3];
    const float* b1   = (const float*)d_in[4];
    const float* W2   = (const float*)d_in[5];
    const float* b2   = (const float*)d_in[6];
    float* out = (float*)d_out;

    __half *xw, *ef, *h1;
    float *dinv, *binv;
    int *cnt_n, *cnt_e, *off_n, *off_e, *adj_n, *adj_e, *aux_n, *aux_e;
    unsigned short *rank_n, *rank_e;
    cudaGetSymbolAddress((void**)&xw,     g_xw);
    cudaGetSymbolAddress((void**)&ef,     g_ef);
    cudaGetSymbolAddress((void**)&h1,     g_h1);
    cudaGetSymbolAddress((void**)&dinv,   g_dinv);
    cudaGetSymbolAddress((void**)&binv,   g_binv);
    cudaGetSymbolAddress((void**)&cnt_n,  g_cnt_n);
    cudaGetSymbolAddress((void**)&cnt_e,  g_cnt_e);
    cudaGetSymbolAddress((void**)&off_n,  g_off_n);
    cudaGetSymbolAddress((void**)&off_e,  g_off_e);
    cudaGetSymbolAddress((void**)&adj_n,  g_adj_n);
    cudaGetSymbolAddress((void**)&adj_e,  g_adj_e);
    cudaGetSymbolAddress((void**)&rank_n, g_rank_n);
    cudaGetSymbolAddress((void**)&rank_e, g_rank_e);
    cudaGetSymbolAddress((void**)&aux_n,  g_aux_n);
    cudaGetSymbolAddress((void**)&aux_e,  g_aux_e);

    cudaFuncSetAttribute(gemm1_kernel,
                         cudaFuncAttributeMaxDynamicSharedMemorySize, G_SMEM);

    // 1: gemm1 (also zeros degree counters)
    gemm1_kernel<<<(N_NODES + G_TR - 1) / G_TR, 256, G_SMEM>>>(x, W1, xw, N_NODES,
                                                               cnt_n, cnt_e);
    // 2-5: degrees + CSR build
    degree_rank_kernel<<<(N_INC + 255) / 256, 256>>>(nidx, eidx, cnt_n, cnt_e,
                                                     rank_n, rank_e, N_INC);
    scan_block2<<<NB_N + NB_E, 1024>>>(cnt_n, off_n, aux_n, dinv,
                                       cnt_e, off_e, aux_e, binv);
    scan_add2<<<NB_N + NB_E, 1024>>>(off_n, aux_n, off_e, aux_e);
    fill_csr<<<(N_INC + 255) / 256, 256>>>(nidx, eidx, off_n, off_e,
                                           rank_n, rank_e, adj_n, adj_e, N_INC);

    // 6-7: layer 1
    gather_kernel<0><<<(N_EDGES + 7) / 8, 256>>>(off_e, adj_e, xw, binv, nullptr, ef, N_EDGES);
    gather_kernel<1><<<(N_NODES + 7) / 8, 256>>>(off_n, adj_n, ef, dinv, b1, h1, N_NODES);

    // 8-9: layer 2 (aggregate in hidden space; W2 post-aggregation)
    gather_kernel<0><<<(N_EDGES + 7) / 8, 256>>>(off_e, adj_e, h1, binv, nullptr, ef, N_EDGES);
    gather_w2_logsoftmax<<<(N_NODES + 7) / 8, 256>>>(off_n, adj_n, ef, dinv, W2, b2, out, N_NODES);
}